// round 1
// baseline (speedup 1.0000x reference)
#include <cuda_runtime.h>

// ---------------- problem constants ----------------
constexpr int B_ = 8;
constexpr int NOBJ = 128;
constexpr int T_ = 12;
constexpr int MC = 2048;
constexpr int E_ = 128;          // EMBED_DIM
constexpr int ID_ = 64;          // IDENTITY_DIM
constexpr int AT_ = 64;          // ATTENTION_DIM
constexpr int H_ = 256;          // HIDDEN_DIM
constexpr int C_ = MC + NOBJ;    // 2176

// ---------------- device scratch ----------------
__device__ float g_dendron[B_ * C_ * E_];
__device__ float g_axon[B_ * C_ * E_];
__device__ float g_ia[B_ * C_ * 128];        // [0:64)=identity, [64:128)=attention (state)
__device__ float g_gath[B_ * C_ * 128];
__device__ float g_am[B_ * C_];
__device__ float g_tmp[B_ * 4 * 128 * 128];  // 4 K-split partials per batch
__device__ float g_meta[T_ * B_ * AT_];
__device__ float g_proj[T_ * B_ * C_];
__device__ float g_args[B_ * T_ * E_];
__device__ float g_w1t[E_ * H_];             // w1 transposed: [k][j]
__device__ float g_w2t[H_ * AT_];            // w2 transposed: [k][j]

// ---------------- build dendron/axon/identity + init attention ----------------
__global__ void k_build(const int* __restrict__ scene,
                        const float* __restrict__ aein, const float* __restrict__ aeout,
                        const float* __restrict__ aeid,
                        const float* __restrict__ cein, const float* __restrict__ ceout,
                        const float* __restrict__ ceid,
                        const float* __restrict__ att_init) {
    int c = blockIdx.x, b = blockIdx.y, d = threadIdx.x;  // d in [0,128)
    float din, ax, idv = 0.f;
    if (c < MC) {
        din = cein[c * E_ + d];
        ax = ceout[c * E_ + d];
        if (d < ID_) idv = ceid[c * ID_ + d];
    } else {
        int o = c - MC;
        float s_in = 0.f, s_out = 0.f, s_id = 0.f;
        #pragma unroll
        for (int a = 0; a < 4; a++) {
            int idx = scene[(b * NOBJ + o) * 4 + a];
            if (idx != -1) {
                s_in += aein[(idx + 1) * E_ + d];
                s_out += aeout[(idx + 1) * E_ + d];
                if (d < ID_) s_id += aeid[(idx + 1) * ID_ + d];
            }
        }
        din = s_in; ax = s_out; idv = s_id;
    }
    long off = (long)(b * C_ + c);
    g_dendron[off * E_ + d] = din;
    g_axon[off * E_ + d] = ax;
    if (d < ID_) g_ia[off * 128 + d] = idv;
    else         g_ia[off * 128 + d] = att_init[d - ID_];
}

// ---------------- transpose axon MLP weights ----------------
__global__ void k_wt(const float* __restrict__ w1, const float* __restrict__ w2) {
    int tid = blockIdx.x * 256 + threadIdx.x;
    for (int i = tid; i < H_ * E_; i += gridDim.x * 256) {
        int j = i / E_, k = i % E_;
        g_w1t[k * H_ + j] = w1[i];
    }
    for (int i = tid; i < AT_ * H_; i += gridDim.x * 256) {
        int j = i / H_, k = i % H_;
        g_w2t[k * AT_ + j] = w2[i];
    }
}

// ---------------- gather arguments + run meta recurrence (per-batch block) ----------------
__global__ void k_args_meta(const int* __restrict__ parg, const int* __restrict__ pop,
                            const float* __restrict__ ceout, const float* __restrict__ att_init,
                            const float* __restrict__ mw1, const float* __restrict__ mb1,
                            const float* __restrict__ mw2, const float* __restrict__ mb2) {
    int b = blockIdx.x;
    int tid = threadIdx.x;
    __shared__ float meta_s[AT_];
    __shared__ float xbuf[E_ + AT_];   // 192
    __shared__ float hbuf[H_];

    // gather this batch's arguments
    for (int i = tid; i < T_ * E_; i += 256) {
        int t = i / E_, d = i % E_;
        g_args[(b * T_ + t) * E_ + d] = ceout[parg[b * T_ + t] * E_ + d];
    }
    if (tid < AT_) meta_s[tid] = att_init[tid];
    __syncthreads();

    for (int t = 0; t < T_; t++) {
        if (tid < AT_) xbuf[tid] = meta_s[tid];
        else if (tid < AT_ + E_) xbuf[tid] = g_args[(b * T_ + t) * E_ + tid - AT_];
        __syncthreads();
        float acc = mb1[tid];
        #pragma unroll 4
        for (int k = 0; k < AT_ + E_; k++) acc += xbuf[k] * mw1[tid * (AT_ + E_) + k];
        hbuf[tid] = fmaxf(acc, 0.f);
        __syncthreads();
        if (tid < AT_) {
            float o = mb2[tid];
            #pragma unroll 4
            for (int k = 0; k < H_; k++) o += hbuf[k] * mw2[tid * H_ + k];
            float m = (pop[b * T_ + t] == 0) ? 1.f : 0.f;
            float nv = m * o + (1.f - m) * meta_s[tid];
            meta_s[tid] = nv;
            g_meta[(t * B_ + b) * AT_ + tid] = nv;
        }
        __syncthreads();
    }
}

// ---------------- proj[t,b,c] = dot(arg[b,t], axon[b,c]) / 128  (warp per output) ----------------
__global__ void k_proj() {
    int gw = (blockIdx.x * 256 + threadIdx.x) >> 5;
    int lane = threadIdx.x & 31;
    if (gw >= T_ * B_ * C_) return;
    int c = gw % C_;
    int tb = gw / C_;               // t*B + b
    int b = tb % B_, t = tb / B_;
    const float* ar = &g_args[(b * T_ + t) * E_];
    const float* ax = &g_axon[((long)(b * C_ + c)) * E_];
    float s = 0.f;
    #pragma unroll
    for (int k = lane; k < E_; k += 32) s += ar[k] * ax[k];
    #pragma unroll
    for (int o = 16; o; o >>= 1) s += __shfl_xor_sync(0xffffffffu, s, o);
    if (lane == 0) g_proj[tb * C_ + c] = s * (1.f / (float)E_);
}

// ---------------- ins_hist (all timesteps, attention-independent) ----------------
__global__ void k_ins(float* __restrict__ out_ins) {
    int idx = blockIdx.x * 256 + threadIdx.x;       // exactly T*B*C*AT threads
    int a = idx & (AT_ - 1);
    int rest = idx >> 6;
    int c = rest % C_;
    int tb = rest / C_;
    out_ins[idx] = g_meta[tb * AT_ + a] * g_proj[tb * C_ + c];
}

// ---------------- am[b,c] = mean_a attention  (warp per row) ----------------
__global__ void k_am() {
    int w = (blockIdx.x * 256 + threadIdx.x) >> 5;
    int lane = threadIdx.x & 31;
    if (w >= B_ * C_) return;
    const float* p = &g_ia[(long)w * 128 + ID_];
    float s = p[lane] + p[lane + 32];
    #pragma unroll
    for (int o = 16; o; o >>= 1) s += __shfl_xor_sync(0xffffffffu, s, o);
    if (lane == 0) g_am[w] = s * (1.f / (float)AT_);
}

// ---------------- tmp[e,d] = sum_c (am[c]*axon[c,e]) * ia[c,d],  K-split by 4 ----------------
// grid: (4, 4, B*4); 32x32 output tile per block; 2x2 per thread; chunk = 544 rows of C
__global__ void k_tmp() {
    __shared__ float sA[32][33];
    __shared__ float sB[32][33];
    int et = blockIdx.x * 32, dt = blockIdx.y * 32;
    int bkc = blockIdx.z;
    int b = bkc >> 2, kc = bkc & 3;
    int cbase = kc * (C_ / 4);                  // 544
    int tid = threadIdx.x;
    int ty = tid >> 4, tx = tid & 15;
    float a00 = 0.f, a01 = 0.f, a10 = 0.f, a11 = 0.f;

    for (int ct = 0; ct < C_ / 4; ct += 32) {
        #pragma unroll
        for (int r = 0; r < 4; r++) {
            int i = tid + r * 256;
            int row = i >> 5, col = i & 31;
            int c = cbase + ct + row;
            float amv = g_am[b * C_ + c];
            sA[row][col] = g_axon[((long)(b * C_ + c)) * E_ + et + col] * amv;
            sB[row][col] = g_ia[((long)(b * C_ + c)) * 128 + dt + col];
        }
        __syncthreads();
        #pragma unroll
        for (int k = 0; k < 32; k++) {
            float x0 = sA[k][ty], x1 = sA[k][ty + 16];
            float y0 = sB[k][tx], y1 = sB[k][tx + 16];
            a00 += x0 * y0; a01 += x0 * y1; a10 += x1 * y0; a11 += x1 * y1;
        }
        __syncthreads();
    }
    float* o = &g_tmp[(long)(b * 4 + kc) * 16384];
    o[(et + ty) * 128 + dt + tx] = a00;
    o[(et + ty) * 128 + dt + tx + 16] = a01;
    o[(et + ty + 16) * 128 + dt + tx] = a10;
    o[(et + ty + 16) * 128 + dt + tx + 16] = a11;
}

// ---------------- gathered = dendron @ tmp / C ----------------
// grid (34, B); block 256; dynamic smem: sD 64x128 + sT 128x128 = 96 KB
__global__ void k_gath() {
    extern __shared__ float sm[];
    float* sD = sm;              // [64][128]
    float* sT = sm + 64 * 128;   // [128][128]
    int cb = blockIdx.x * 64;
    int b = blockIdx.y;
    int tid = threadIdx.x;

    // stage tmp: sum the 4 K-split partials
    {
        const float4* p = (const float4*)&g_tmp[(long)b * 4 * 16384];
        float4* d = (float4*)sT;
        for (int i = tid; i < 4096; i += 256) {
            float4 v0 = p[i], v1 = p[i + 4096], v2 = p[i + 8192], v3 = p[i + 12288];
            d[i] = make_float4(v0.x + v1.x + v2.x + v3.x, v0.y + v1.y + v2.y + v3.y,
                               v0.z + v1.z + v2.z + v3.z, v0.w + v1.w + v2.w + v3.w);
        }
    }
    {
        const float4* p = (const float4*)&g_dendron[((long)(b * C_ + cb)) * E_];
        float4* d = (float4*)sD;
        for (int i = tid; i < 2048; i += 256) d[i] = p[i];
    }
    __syncthreads();

    int rg = tid >> 4, dg = tid & 15;   // 4 rows, 8 cols per thread
    float acc[4][8];
    #pragma unroll
    for (int r = 0; r < 4; r++)
        #pragma unroll
        for (int i = 0; i < 8; i++) acc[r][i] = 0.f;

    for (int e = 0; e < 128; e++) {
        float a0 = sD[(rg * 4 + 0) * 128 + e];
        float a1 = sD[(rg * 4 + 1) * 128 + e];
        float a2 = sD[(rg * 4 + 2) * 128 + e];
        float a3 = sD[(rg * 4 + 3) * 128 + e];
        float4 v0 = *(const float4*)&sT[e * 128 + dg * 8];
        float4 v1 = *(const float4*)&sT[e * 128 + dg * 8 + 4];
        float bv[8] = {v0.x, v0.y, v0.z, v0.w, v1.x, v1.y, v1.z, v1.w};
        #pragma unroll
        for (int i = 0; i < 8; i++) {
            acc[0][i] += a0 * bv[i];
            acc[1][i] += a1 * bv[i];
            acc[2][i] += a2 * bv[i];
            acc[3][i] += a3 * bv[i];
        }
    }
    const float sc = 1.f / (float)C_;
    #pragma unroll
    for (int r = 0; r < 4; r++) {
        float4 s0 = make_float4(acc[r][0] * sc, acc[r][1] * sc, acc[r][2] * sc, acc[r][3] * sc);
        float4 s1 = make_float4(acc[r][4] * sc, acc[r][5] * sc, acc[r][6] * sc, acc[r][7] * sc);
        float* o = &g_gath[((long)(b * C_ + cb + rg * 4 + r)) * 128 + dg * 8];
        *(float4*)o = s0;
        *(float4*)(o + 4) = s1;
    }
}

// ---------------- MLP + attention update + history writes (8 rows per block) ----------------
__global__ void k_mlp(int t, const int* __restrict__ pop,
                      const float* __restrict__ b1v, const float* __restrict__ b2v,
                      float* __restrict__ att_hist, float* __restrict__ trans_hist) {
    __shared__ __align__(16) float gs[8][128];
    __shared__ __align__(16) float h_s[8][256];
    int tid = threadIdx.x;
    int row_base = blockIdx.x * 8;

    {
        const float4* src = (const float4*)&g_gath[(long)row_base * 128];
        float4* dst = (float4*)&gs[0][0];
        for (int i = tid; i < 8 * 128 / 4; i += 256) dst[i] = src[i];
    }
    __syncthreads();

    // layer 1: thread j computes h[r][j] for 8 rows
    int j = tid;
    float acc[8];
    float bb = b1v[j];
    #pragma unroll
    for (int r = 0; r < 8; r++) acc[r] = bb;
    for (int k = 0; k < 128; k += 4) {
        float w0 = g_w1t[(k + 0) * H_ + j];
        float w1 = g_w1t[(k + 1) * H_ + j];
        float w2 = g_w1t[(k + 2) * H_ + j];
        float w3 = g_w1t[(k + 3) * H_ + j];
        #pragma unroll
        for (int r = 0; r < 8; r++) {
            float4 g4 = *(const float4*)&gs[r][k];
            acc[r] += g4.x * w0 + g4.y * w1 + g4.z * w2 + g4.w * w3;
        }
    }
    #pragma unroll
    for (int r = 0; r < 8; r++) h_s[r][j] = fmaxf(acc[r], 0.f);
    __syncthreads();

    // layer 2: j2 = tid%64 output, rows rr and rr+4
    int j2 = tid & 63, rr = tid >> 6;
    float o0 = b2v[j2], o1 = o0;
    for (int k = 0; k < 256; k += 4) {
        float w0 = g_w2t[(k + 0) * AT_ + j2];
        float w1 = g_w2t[(k + 1) * AT_ + j2];
        float w2 = g_w2t[(k + 2) * AT_ + j2];
        float w3 = g_w2t[(k + 3) * AT_ + j2];
        float4 ha = *(const float4*)&h_s[rr][k];
        float4 hb = *(const float4*)&h_s[rr + 4][k];
        o0 += ha.x * w0 + ha.y * w1 + ha.z * w2 + ha.w * w3;
        o1 += hb.x * w0 + hb.y * w1 + hb.z * w2 + hb.w * w3;
    }

    #pragma unroll
    for (int p = 0; p < 2; p++) {
        int r = (p == 0) ? rr : rr + 4;
        float o = (p == 0) ? o0 : o1;
        int bc = row_base + r;
        int b = bc / C_, c = bc % C_;
        float transfer = o + gs[r][ID_ + j2];
        int op = pop[b * T_ + t];
        float insv = (op == 1) ? 1.f : 0.f;
        float trv = (op == 2) ? 1.f : 0.f;
        float insert = g_meta[(t * B_ + b) * AT_ + j2] * g_proj[(t * B_ + b) * C_ + c];
        float a = g_ia[(long)bc * 128 + ID_ + j2];
        a += insv * insert + trv * transfer;
        a = (a >= 0.f) ? a : 0.01f * a;
        a = fminf(fmaxf(a, -1.f), 2.f);
        g_ia[(long)bc * 128 + ID_ + j2] = a;
        int hidx = ((t * B_ + b) * C_ + c) * AT_ + j2;
        att_hist[hidx] = a;
        trans_hist[hidx] = transfer;
    }
}

// ---------------- final log-softmax over C of mean attention ----------------
__global__ void k_final(float* __restrict__ out) {
    int b = blockIdx.x, tid = threadIdx.x;
    __shared__ float m_s[C_];
    __shared__ float red[256];
    for (int c = tid; c < C_; c += 256) {
        const float* p = &g_ia[((long)(b * C_ + c)) * 128 + ID_];
        float s = 0.f;
        #pragma unroll 8
        for (int a = 0; a < AT_; a++) s += p[a];
        m_s[c] = s * (1.f / (float)AT_);
    }
    __syncthreads();
    float mx = -1e30f;
    for (int c = tid; c < C_; c += 256) mx = fmaxf(mx, m_s[c]);
    red[tid] = mx;
    __syncthreads();
    for (int s = 128; s; s >>= 1) {
        if (tid < s) red[tid] = fmaxf(red[tid], red[tid + s]);
        __syncthreads();
    }
    mx = red[0];
    __syncthreads();
    float se = 0.f;
    for (int c = tid; c < C_; c += 256) se += expf(m_s[c] - mx);
    red[tid] = se;
    __syncthreads();
    for (int s = 128; s; s >>= 1) {
        if (tid < s) red[tid] += red[tid + s];
        __syncthreads();
    }
    float lse = logf(red[0]);
    __syncthreads();
    for (int c = tid; c < C_; c += 256) out[b * C_ + c] = m_s[c] - mx - lse;
}

// ---------------- launch ----------------
extern "C" void kernel_launch(void* const* d_in, const int* in_sizes, int n_in,
                              void* d_out, int out_size) {
    (void)in_sizes; (void)n_in; (void)out_size;
    const int* scene     = (const int*)d_in[0];
    const int* prog_op   = (const int*)d_in[1];
    const int* prog_arg  = (const int*)d_in[2];
    const float* aein    = (const float*)d_in[3];
    const float* aeout   = (const float*)d_in[4];
    const float* aeid    = (const float*)d_in[5];
    const float* cein    = (const float*)d_in[6];
    const float* ceout   = (const float*)d_in[7];
    const float* ceid    = (const float*)d_in[8];
    const float* att_init = (const float*)d_in[11];
    const float* axw1    = (const float*)d_in[12];
    const float* axb1    = (const float*)d_in[13];
    const float* axw2    = (const float*)d_in[14];
    const float* axb2    = (const float*)d_in[15];
    const float* mw1     = (const float*)d_in[16];
    const float* mb1     = (const float*)d_in[17];
    const float* mw2     = (const float*)d_in[18];
    const float* mb2     = (const float*)d_in[19];

    float* out = (float*)d_out;
    float* att_hist = out + B_ * C_;
    float* ins_hist = att_hist + (long)T_ * B_ * C_ * AT_;
    float* trans_hist = ins_hist + (long)T_ * B_ * C_ * AT_;

    cudaFuncSetAttribute(k_gath, cudaFuncAttributeMaxDynamicSharedMemorySize, 98304);

    k_build<<<dim3(C_, B_), 128>>>(scene, aein, aeout, aeid, cein, ceout, ceid, att_init);
    k_wt<<<64, 256>>>(axw1, axw2);
    k_args_meta<<<B_, 256>>>(prog_arg, prog_op, ceout, att_init, mw1, mb1, mw2, mb2);
    k_proj<<<(T_ * B_ * C_ * 32) / 256, 256>>>();
    k_ins<<<(T_ * B_ * C_ * AT_) / 256, 256>>>(ins_hist);

    for (int t = 0; t < T_; t++) {
        k_am<<<(B_ * C_) / 8, 256>>>();
        k_tmp<<<dim3(4, 4, B_ * 4), 256>>>();
        k_gath<<<dim3(C_ / 64, B_), 256, 98304>>>();
        k_mlp<<<(B_ * C_) / 8, 256>>>(t, prog_op, axb1, axb2, att_hist, trans_hist);
    }
    k_final<<<B_, 256>>>(out);
}